// round 15
// baseline (speedup 1.0000x reference)
#include <cuda_runtime.h>
#include <cuda_fp16.h>
#include <math.h>

#define NN 1024
#define NPG 128
#define NB 8
#define KM 64
#define H 600
#define G 50
#define NL 6
#define NC 259           // coarse knots, d=(q-1)*D0, q=0..258
#define D0 (10.0f/256.0f)
#define HK 608           // one split block (600 padded to 19*32)
#define K2 1216          // A' width: [hi(608) | lo(608)]
#define NIT2 38          // K2/32 (2-term)
#define NIT1 19          // HK/32 (1-term, bgemm0)
#define MT 320           // padded M for table gemm

// ---------------- device scratch (zero-initialized at module load) ----------------
__device__ __align__(16) float g_h[NN*H];
__device__ __align__(16) __half g_x1h[NN*H];
__device__ __align__(16) __half g_As0[(size_t)NN*K2];    // h split
__device__ __align__(16) __half g_As1[(size_t)NN*K2];    // msg split
__device__ __align__(16) __half g_As2[(size_t)NN*K2];    // m1 split
__device__ __align__(16) __half g_Ast[(size_t)NL*MT*K2]; // tmp split (table)
__device__ __align__(16) __half g_Bw[(size_t)18*HK*H + 1024];  // lin1,l2w,ilw (fp16)
__device__ __align__(16) __half g_Bw2[(size_t)NL*HK*H + 1024]; // w2 (fp16)
__device__ __align__(16) float g_ea[NC*G], g_C[NC];
__device__ __align__(16) __half g_Th[NL*NC*H];   // coarse fp16 filter tables
__device__ int   g_nbr[NN*KM], g_base[NN*KM], g_cnt[NN];
__device__ __align__(16) float g_w4[NN*KM*4];

__device__ __forceinline__ float sspf(float x){
    float r = (x > 0.f) ? (x + log1pf(expf(-x))) : log1pf(expf(x));
    return r - 0.69314718055994530942f;
}

// A' split store (half2): hi block at 0, lo block at +608
__device__ __forceinline__ void split_store(__half* base, size_t off,
                                            float v0, float v1){
    __half2 hi2 = __floats2half2_rn(v0, v1);
    __half2 lo2 = __floats2half2_rn(v0 - __half2float(__low2half(hi2)),
                                    v1 - __half2float(__high2half(hi2)));
    __half2* dp = reinterpret_cast<__half2*>(base + off);
    dp[0]   = hi2;
    dp[304] = lo2;
}

// unpack uint2 (4 fp16) -> float4
__device__ __forceinline__ float4 h4f(uint2 u){
    __half2 p0 = *reinterpret_cast<__half2*>(&u.x);
    __half2 p1 = *reinterpret_cast<__half2*>(&u.y);
    float2 f0 = __half22float2(p0), f1 = __half22float2(p1);
    return make_float4(f0.x, f0.y, f1.x, f1.y);
}

// ---- graph build: 1 block per node, matches jax top_k(-dist2, K); cubic weights ----
__global__ void build_graph(const float* __restrict__ pos){
    int i = blockIdx.x, b = i/NPG, il = i - b*NPG, j = threadIdx.x;
    __shared__ float sx[NPG], sy[NPG], sz[NPG], sd2[NPG];
    __shared__ int scnt;
    const float* pg = pos + (size_t)b*NPG*3;
    sx[j]=pg[j*3]; sy[j]=pg[j*3+1]; sz[j]=pg[j*3+2];
    if(j==0) scnt=0;
    __syncthreads();
    float dx=__fsub_rn(sx[il],sx[j]), dy=__fsub_rn(sy[il],sy[j]), dz=__fsub_rn(sz[il],sz[j]);
    float d2=__fadd_rn(__fadd_rn(__fmul_rn(dx,dx),__fmul_rn(dy,dy)),__fmul_rn(dz,dz));
    bool ok = (d2<=100.0f) && (j!=il);
    sd2[j] = ok ? d2 : 3.0e38f;
    __syncthreads();
    int rank=0;
    if(ok){
        #pragma unroll 8
        for(int t=0;t<NPG;t++){ float o=sd2[t]; rank += (o<d2)||(o==d2 && t<j); }
        atomicAdd(&scnt,1);
    }
    __syncthreads();
    if(j==0) g_cnt[i] = min(scnt,KM);
    if(ok && rank<KM){
        float d = sqrtf(d2);
        float u = d * (1.0f/D0);
        int s = (int)u; if(s>255) s=255; if(s<0) s=0;
        float t = u - (float)s;
        float t2=t*t, t3=t2*t;
        int e=i*KM+rank;
        g_nbr[e]=b*NPG+j; g_base[e]=s*H;
        g_w4[e*4+0]=0.5f*(-t3+2.f*t2-t);
        g_w4[e*4+1]=0.5f*(3.f*t3-5.f*t2+2.f);
        g_w4[e*4+2]=0.5f*(-3.f*t3+4.f*t2+t);
        g_w4[e*4+3]=0.5f*(t3-t2);
    }
}

// ---- gaussian smearing + cosine cutoff on coarse grid ----
__global__ void smear(){
    int idx = blockIdx.x*blockDim.x + threadIdx.x;
    if(idx >= NC*G) return;
    int q = idx/G, g = idx - q*G;
    float d = (float)(q-1)*D0;
    float step = 10.0f/49.0f;
    float x = d - (float)g*step;
    g_ea[idx] = expf((-0.5f/(step*step))*x*x);
    if(g==0) g_C[q] = 0.5f*(cosf(d*0.31415926535897932f)+1.0f);
}

// ---- embedding gather + h split ----
__global__ void embed(const float* __restrict__ emb, const int* __restrict__ z){
    int idx = blockIdx.x*blockDim.x + threadIdx.x;
    if(idx >= NN*H) return;
    int i = idx/H, c = idx - i*H;
    float v = emb[z[i]*H + c];
    g_h[idx] = v;
    __half hi = __float2half_rn(v);
    g_As0[(size_t)i*K2 + c]      = hi;
    g_As0[(size_t)i*K2 + HK + c] = __float2half_rn(v - __half2float(hi));
}

// ---- weight convert: 24 [600,600] fp32 -> fp16, float4 vectorized ----
__global__ void wsplit(const float* __restrict__ lin1, const float* __restrict__ l2w,
                       const float* __restrict__ ilw, const float* __restrict__ w2){
    int idx = blockIdx.x*blockDim.x + threadIdx.x;
    const int PM = H*H/4;   // 90000 float4 per matrix
    if(idx >= 24*PM) return;
    int w = idx/PM, e4 = idx - w*PM;
    int r = e4/150, c = (e4 - r*150)*4;
    int l = w>>2, kind = w&3;
    const float* src = (kind==0) ? lin1 : (kind==1) ? l2w : (kind==2) ? ilw : w2;
    float4 v = *reinterpret_cast<const float4*>(src + (size_t)l*H*H + (size_t)r*H + c);
    __half* dst = (kind<3) ? (g_Bw + (size_t)(l*3+kind)*HK*H)
                           : (g_Bw2 + (size_t)l*HK*H);
    __half2* d2 = reinterpret_cast<__half2*>(dst + (size_t)r*H + c);
    d2[0] = __floats2half2_rn(v.x, v.y);
    d2[1] = __floats2half2_rn(v.z, v.w);
}

// ---- aggregation: cubic interp fp16 table * fp16 x1; 4 cols/thread, 8B loads ----
__global__ void __launch_bounds__(192) agg(int l){
    int i = blockIdx.x, t = threadIdx.x;
    __shared__ int s_j[KM], s_b[KM], s_cnt;
    __shared__ float4 s_w[KM];
    if(t==0) s_cnt = g_cnt[i];
    if(t<KM){
        int e=i*KM+t;
        s_j[t]=g_nbr[e]*H; s_b[t]=g_base[e];
        s_w[t]=*reinterpret_cast<const float4*>(&g_w4[e*4]);
    }
    __syncthreads();
    if(t >= 150) return;
    int h = t*4;
    const __half* T = g_Th + (size_t)l*NC*H;
    int cnt = s_cnt;
    float a0=0.f, a1=0.f, a2=0.f, a3=0.f;
    #pragma unroll 2
    for(int k=0;k<cnt;k++){
        const __half* tp = T + s_b[k] + h;
        float4 t0 = h4f(__ldg(reinterpret_cast<const uint2*>(tp)));
        float4 t1 = h4f(__ldg(reinterpret_cast<const uint2*>(tp + 600)));
        float4 t2 = h4f(__ldg(reinterpret_cast<const uint2*>(tp + 1200)));
        float4 t3 = h4f(__ldg(reinterpret_cast<const uint2*>(tp + 1800)));
        float4 xx = h4f(__ldg(reinterpret_cast<const uint2*>(&g_x1h[s_j[k] + h])));
        float4 w = s_w[k];
        float v0 = w.x*t0.x + w.y*t1.x + w.z*t2.x + w.w*t3.x;
        float v1 = w.x*t0.y + w.y*t1.y + w.z*t2.y + w.w*t3.y;
        float v2 = w.x*t0.z + w.y*t1.z + w.z*t2.z + w.w*t3.z;
        float v3 = w.x*t0.w + w.y*t1.w + w.z*t2.w + w.w*t3.w;
        a0 = fmaf(v0, xx.x, a0);
        a1 = fmaf(v1, xx.y, a1);
        a2 = fmaf(v2, xx.z, a2);
        a3 = fmaf(v3, xx.w, a3);
    }
    size_t off = (size_t)i*K2 + h;
    split_store(g_As1, off,     a0, a1);
    split_store(g_As1, off + 2, a2, a3);
}

// ---- mma / cp.async helpers ----
__device__ __forceinline__ void ldsm4(unsigned* r, unsigned addr){
    asm volatile("ldmatrix.sync.aligned.m8n8.x4.shared.b16 {%0,%1,%2,%3}, [%4];"
        : "=r"(r[0]),"=r"(r[1]),"=r"(r[2]),"=r"(r[3]) : "r"(addr));
}
__device__ __forceinline__ void ldsm4t(unsigned* r, unsigned addr){
    asm volatile("ldmatrix.sync.aligned.m8n8.x4.trans.shared.b16 {%0,%1,%2,%3}, [%4];"
        : "=r"(r[0]),"=r"(r[1]),"=r"(r[2]),"=r"(r[3]) : "r"(addr));
}
__device__ __forceinline__ void mma16816(float* c, const unsigned* a, unsigned b0, unsigned b1){
    asm volatile("mma.sync.aligned.m16n8k16.row.col.f32.f16.f16.f32 "
        "{%0,%1,%2,%3}, {%4,%5,%6,%7}, {%8,%9}, {%0,%1,%2,%3};"
        : "+f"(c[0]),"+f"(c[1]),"+f"(c[2]),"+f"(c[3])
        : "r"(a[0]),"r"(a[1]),"r"(a[2]),"r"(a[3]), "r"(b0),"r"(b1));
}
#define CPA16(dst,src) asm volatile("cp.async.cg.shared.global [%0], [%1], 16;\n"::"r"(dst),"l"(src))
#define CPC()  asm volatile("cp.async.commit_group;\n")
#define CPW2() asm volatile("cp.async.wait_group 2;\n" ::: "memory")
#define CPW0() asm volatile("cp.async.wait_group 0;\n" ::: "memory")

#define ASTG (32*40*2)
#define BSTG (32*72*2)

// 256 threads, 8 warps (2m x 4n), 32x64 CTA tile, warp tile 16x16, 4-stage cp.async.
struct Frag { unsigned aF[2]; unsigned bF[2]; unsigned aD, bD; };

__device__ __forceinline__ Frag make_frag(
        __half (*As)[32][40], __half (*Bs)[32][72],
        int wm, int wn, int lane, int arow, int acol, int brow, int bcol){
    Frag f;
    f.aD = (unsigned)__cvta_generic_to_shared(&As[0][arow][acol]);
    f.bD = (unsigned)__cvta_generic_to_shared(&Bs[0][brow][bcol]);
    #pragma unroll
    for(int s=0;s<2;s++)
        f.aF[s] = (unsigned)__cvta_generic_to_shared(
            &As[0][wm + (lane&15)][s*16 + (lane>>4)*8]);
    #pragma unroll
    for(int s=0;s<2;s++)
        f.bF[s] = (unsigned)__cvta_generic_to_shared(
            &Bs[0][s*16 + (lane&15)][wn + (lane>>4)*8]);
    return f;
}

// NITER k-blocks over A; B has 19 blocks, reused for blocks 19..37
template<int NITER>
__device__ __forceinline__ void gemm_mainloop(
        const __half* aptr, const __half* bptr, bool aload,
        const Frag& f, float acc[2][4]){
    if(aload) CPA16(f.aD, aptr);
    CPA16(f.bD, bptr); CPC();
    if(aload) CPA16(f.aD+ASTG, aptr+32);
    CPA16(f.bD+BSTG, bptr+(size_t)32*H); CPC();
    for(int it=0; it<NITER; it++){
        int pre = it+2;
        if(pre < NITER){
            int sb = pre & 3;
            int bm = (pre < 19) ? pre : pre - 19;
            if(aload) CPA16(f.aD + sb*ASTG, aptr + pre*32);
            CPA16(f.bD + sb*BSTG, bptr + (size_t)(bm*32)*H);
        }
        CPC();
        if(it < NITER-2) CPW2(); else CPW0();
        __syncthreads();
        unsigned ao = (it&3)*ASTG, bo = (it&3)*BSTG;
        #pragma unroll
        for(int s=0;s<2;s++){
            unsigned af[4], bf[4];
            ldsm4 (af, f.aF[s] + ao);
            ldsm4t(bf, f.bF[s] + bo);
            mma16816(acc[0], af, bf[0], bf[1]);
            mma16816(acc[1], af, bf[2], bf[3]);
        }
    }
}

// ---- node GEMM with fused epilogue ----
// EPI 0: -> x1h fp16 (single-term A). EPI 1: ssp(+bias) -> split. EPI 2: +bias+h residual -> h & split.
template<int EPI, int NITER>
__global__ void __launch_bounds__(256) bgemm(const __half* __restrict__ Ap,
        const __half* __restrict__ Bp, const float* __restrict__ bias,
        float* __restrict__ hbuf, __half* __restrict__ sout,
        __half* __restrict__ x1out){
    __shared__ __half As[4][32][40];
    __shared__ __half Bs[4][32][72];
    int tid=threadIdx.x, warp=tid>>5, lane=tid&31;
    int m0=blockIdx.y*32, n0=blockIdx.x*64;
    int wm=(warp>>2)*16, wn=(warp&3)*16;
    int arow=(tid&127)>>2, acol=(tid&3)*8;
    int brow=tid>>3, bcol=(tid&7)*8;
    bool aload = tid < 128;
    Frag f = make_frag(As, Bs, wm, wn, lane, arow, acol, brow, bcol);
    float acc[2][4];
    #pragma unroll
    for(int ni=0;ni<2;ni++)
        #pragma unroll
        for(int q=0;q<4;q++) acc[ni][q]=0.f;
    const __half* aptr = Ap + (size_t)(m0+arow)*K2 + acol;
    const __half* bptr = Bp + (size_t)brow*H + n0 + bcol;
    gemm_mainloop<NITER>(aptr, bptr, aload, f, acc);

    #pragma unroll
    for(int ni=0;ni<2;ni++){
        int c0 = n0 + wn + ni*8 + (lane&3)*2;
        if(c0 >= 600) continue;
        #pragma unroll
        for(int hf=0; hf<2; hf++){
            int r = m0 + wm + (lane>>2) + hf*8;
            float v0 = acc[ni][hf*2], v1 = acc[ni][hf*2+1];
            if(EPI==0){
                *reinterpret_cast<__half2*>(x1out + (size_t)r*H + c0)
                    = __floats2half2_rn(v0, v1);
            } else {
                v0 += bias[c0]; v1 += bias[c0+1];
                if(EPI==1){
                    v0 = sspf(v0); v1 = sspf(v1);
                } else {
                    float2 hv = *reinterpret_cast<float2*>(hbuf + (size_t)r*H + c0);
                    v0 += hv.x; v1 += hv.y;
                    *reinterpret_cast<float2*>(hbuf + (size_t)r*H + c0) = make_float2(v0, v1);
                }
                split_store(sout, (size_t)r*K2 + c0, v0, v1);
            }
        }
    }
}

// ---- table GEMM: per layer, T = (tmp' @ w2 + b2) * C -> fp16 table ----
__global__ void __launch_bounds__(256) tbgemm(const float* __restrict__ b2){
    __shared__ __half As[4][32][40];
    __shared__ __half Bs[4][32][72];
    int zb = blockIdx.z;
    int tid=threadIdx.x, warp=tid>>5, lane=tid&31;
    int m0=blockIdx.y*32, n0=blockIdx.x*64;
    int wm=(warp>>2)*16, wn=(warp&3)*16;
    int arow=(tid&127)>>2, acol=(tid&3)*8;
    int brow=tid>>3, bcol=(tid&7)*8;
    bool aload = tid < 128;
    Frag f = make_frag(As, Bs, wm, wn, lane, arow, acol, brow, bcol);
    float acc[2][4];
    #pragma unroll
    for(int ni=0;ni<2;ni++)
        #pragma unroll
        for(int q=0;q<4;q++) acc[ni][q]=0.f;
    const __half* aptr = g_Ast + (size_t)zb*MT*K2 + (size_t)(m0+arow)*K2 + acol;
    const __half* bptr = g_Bw2 + (size_t)zb*HK*H + (size_t)brow*H + n0 + bcol;
    gemm_mainloop<NIT2>(aptr, bptr, aload, f, acc);

    const float* bias = b2 + (size_t)zb*H;
    #pragma unroll
    for(int ni=0;ni<2;ni++){
        int c0 = n0 + wn + ni*8 + (lane&3)*2;
        if(c0 >= 600) continue;
        #pragma unroll
        for(int hf=0; hf<2; hf++){
            int r = m0 + wm + (lane>>2) + hf*8;
            if(r >= NC) continue;
            float cc = g_C[r];
            float v0 = (acc[ni][hf*2]   + bias[c0])   * cc;
            float v1 = (acc[ni][hf*2+1] + bias[c0+1]) * cc;
            *reinterpret_cast<__half2*>(g_Th + (size_t)zb*NC*H + (size_t)r*H + c0)
                = __floats2half2_rn(v0, v1);
        }
    }
}

// ---- table stage-1 (K=50) FFMA GEMM, epilogue: ssp + direct fp16 split ----
__global__ void __launch_bounds__(256) sgemm1(const float* __restrict__ w1,
        const float* __restrict__ b1){
    int zb = blockIdx.z;
    const float* A = g_ea;
    const float* B = w1 + (size_t)zb*G*H;
    const float* bias = b1 + (size_t)zb*H;
    const int BM=64, BN=64, BK=10;
    __shared__ float As[BK][BM], Bs[BK][BN];
    int tid=threadIdx.x, tx=tid&15, ty=tid>>4;
    int m0=blockIdx.y*BM, n0=blockIdx.x*BN;
    int ar=tid&63, ac=tid>>6;
    int br=tid>>6, bc=(tid&63);
    float acc[4][4];
    #pragma unroll
    for(int a=0;a<4;a++)
        #pragma unroll
        for(int c=0;c<4;c++) acc[a][c]=0.f;
    for(int k0=0;k0<G;k0+=BK){
        #pragma unroll
        for(int u=0;u<3;u++){
            int kk = ac + u*4;
            if(kk<BK){
                int gm=m0+ar, gk=k0+kk;
                As[kk][ar] = (gm<NC && gk<G) ? A[(size_t)gm*G+gk] : 0.f;
            }
        }
        #pragma unroll
        for(int u=0;u<3;u++){
            int kk = br + u*4;
            if(kk<BK){
                int gk=k0+kk, gn=n0+bc;
                Bs[kk][bc] = (gk<G && gn<H) ? B[(size_t)gk*H+gn] : 0.f;
            }
        }
        __syncthreads();
        #pragma unroll
        for(int kk=0;kk<BK;kk++){
            float4 av=*reinterpret_cast<const float4*>(&As[kk][ty<<2]);
            float4 bv=*reinterpret_cast<const float4*>(&Bs[kk][tx<<2]);
            float a0=av.x,a1=av.y,a2=av.z,a3=av.w;
            float b0=bv.x,b1=bv.y,b2=bv.z,b3=bv.w;
            acc[0][0]=fmaf(a0,b0,acc[0][0]); acc[0][1]=fmaf(a0,b1,acc[0][1]);
            acc[0][2]=fmaf(a0,b2,acc[0][2]); acc[0][3]=fmaf(a0,b3,acc[0][3]);
            acc[1][0]=fmaf(a1,b0,acc[1][0]); acc[1][1]=fmaf(a1,b1,acc[1][1]);
            acc[1][2]=fmaf(a1,b2,acc[1][2]); acc[1][3]=fmaf(a1,b3,acc[1][3]);
            acc[2][0]=fmaf(a2,b0,acc[2][0]); acc[2][1]=fmaf(a2,b1,acc[2][1]);
            acc[2][2]=fmaf(a2,b2,acc[2][2]); acc[2][3]=fmaf(a2,b3,acc[2][3]);
            acc[3][0]=fmaf(a3,b0,acc[3][0]); acc[3][1]=fmaf(a3,b1,acc[3][1]);
            acc[3][2]=fmaf(a3,b2,acc[3][2]); acc[3][3]=fmaf(a3,b3,acc[3][3]);
        }
        __syncthreads();
    }
    #pragma unroll
    for(int ii=0;ii<4;ii++){
        int m=m0+(ty<<2)+ii;
        if(m>=NC) continue;
        __half* row = g_Ast + (size_t)(zb*MT + m)*K2;
        #pragma unroll
        for(int jj=0;jj<4;jj++){
            int n=n0+(tx<<2)+jj;
            if(n>=H) continue;
            float v = sspf(acc[ii][jj] + bias[n]);
            __half hi = __float2half_rn(v);
            row[n]      = hi;
            row[HK + n] = __float2half_rn(v - __half2float(hi));
        }
    }
}

// ---- fused mean-pool + final linear ----
__global__ void __launch_bounds__(600) poolfin(const float* __restrict__ pw,
        const float* __restrict__ pb, float* __restrict__ out){
    int b = blockIdx.x, h = threadIdx.x;
    __shared__ float sp[H];
    const float* p = g_h + (size_t)b*NPG*H + h;
    float s = 0.f;
    #pragma unroll 8
    for(int n=0;n<NPG;n++) s += p[(size_t)n*H];
    sp[h] = s * (1.0f/NPG);
    __syncthreads();
    float o = pb[h];
    for(int k=0;k<H;k++) o = fmaf(sp[k], pw[(size_t)k*H+h], o);
    out[(size_t)b*H + h] = o;
}

extern "C" void kernel_launch(void* const* d_in, const int* in_sizes, int n_in,
                              void* d_out, int out_size){
    // dict order: z,pos,emb,w1,b1,w2,b2,lin1,l2w,l2b,ilw,ilb,pw,pb
    int map[14] = {0,1,2,3,4,5,6,7,8,9,10,11,12,13};
    if(!(in_sizes[0]==1024 && in_sizes[1]==3072)){
        int sig[14] = {13,0,1,2,3,4,5,6,7,8,9,10,11,12};
        for(int i=0;i<14;i++) map[i]=sig[i];
    }
    const int*   z    = (const int*)  d_in[map[0]];
    const float* posv = (const float*)d_in[map[1]];
    const float* emb  = (const float*)d_in[map[2]];
    const float* w1   = (const float*)d_in[map[3]];
    const float* b1   = (const float*)d_in[map[4]];
    const float* w2   = (const float*)d_in[map[5]];
    const float* b2   = (const float*)d_in[map[6]];
    const float* lin1 = (const float*)d_in[map[7]];
    const float* l2w  = (const float*)d_in[map[8]];
    const float* l2b  = (const float*)d_in[map[9]];
    const float* ilw  = (const float*)d_in[map[10]];
    const float* ilb  = (const float*)d_in[map[11]];
    const float* pw   = (const float*)d_in[map[12]];
    const float* pb   = (const float*)d_in[map[13]];
    float* out = (float*)d_out;

    float *p_h;
    __half *p_As0,*p_As1,*p_As2,*p_Bw,*p_x1h;
    cudaGetSymbolAddress((void**)&p_h,   g_h);
    cudaGetSymbolAddress((void**)&p_As0, g_As0);
    cudaGetSymbolAddress((void**)&p_As1, g_As1);
    cudaGetSymbolAddress((void**)&p_As2, g_As2);
    cudaGetSymbolAddress((void**)&p_Bw,  g_Bw);
    cudaGetSymbolAddress((void**)&p_x1h, g_x1h);

    build_graph<<<NN, NPG>>>(posv);
    smear<<<(NC*G+255)/256, 256>>>();
    embed<<<(NN*H+255)/256, 256>>>(emb, z);
    wsplit<<<(24*H*H/4+255)/256, 256>>>(lin1, l2w, ilw, w2);

    // table build: stage-1 FFMA (K=50, fused split) -> tensor-core stage-2
    dim3 gT1((H+63)/64, (NC+63)/64, NL);
    sgemm1<<<gT1, 256>>>(w1, b1);
    dim3 gTB((H+63)/64, MT/32, NL);   // 10 x 10 x 6
    tbgemm<<<gTB, 256>>>(b2);

    dim3 gG(10, 32);   // 320 blocks
    for(int l=0;l<NL;l++){
        const __half* Blin1 = p_Bw + (size_t)(l*3+0)*HK*H;
        const __half* Bl2w  = p_Bw + (size_t)(l*3+1)*HK*H;
        const __half* Bilw  = p_Bw + (size_t)(l*3+2)*HK*H;
        // x1 = h @ lin1 -> fp16 (hi-only A, K'=608)
        bgemm<0,NIT1><<<gG,256>>>(p_As0, Blin1, nullptr, nullptr, nullptr, p_x1h);
        agg<<<NN, 192>>>(l);
        // m1 = ssp(msg @ l2w + l2b) -> split (2-term A)
        bgemm<1,NIT2><<<gG,256>>>(p_As1, Bl2w, l2b+(size_t)l*H, nullptr, p_As2, nullptr);
        // h = h + (m1 @ ilw + ilb); emits h split for next layer
        bgemm<2,NIT2><<<gG,256>>>(p_As2, Bilw, ilb+(size_t)l*H, p_h, p_As0, nullptr);
    }
    poolfin<<<NB, H>>>(pw, pb, out);
}

// round 16
// speedup vs baseline: 1.1349x; 1.1349x over previous
#include <cuda_runtime.h>
#include <cuda_fp16.h>
#include <math.h>

#define NN 1024
#define NPG 128
#define NB 8
#define KM 64
#define H 600
#define G 50
#define NL 6
#define NC 259           // coarse knots, d=(q-1)*D0, q=0..258
#define D0 (10.0f/256.0f)
#define HK 608           // one split block (600 padded to 19*32)
#define K2 1216          // A' width: [hi(608) | lo(608)]
#define NIT2 38          // K2/32 (2-term)
#define NIT1 19          // HK/32 (1-term)
#define MT 320           // padded M for table gemm

// setup mega-kernel block ranges
#define SB_SMEAR   NN
#define NB_SMEAR   51          // ceil(NC*G/256)
#define SB_EMBED   (SB_SMEAR + NB_SMEAR)
#define NB_EMBED   2400        // NN*H/256
#define SB_WSPLIT  (SB_EMBED + NB_EMBED)
#define NB_WSPLIT  8438        // ceil(24*H*H/4/256)
#define NB_SETUP   (SB_WSPLIT + NB_WSPLIT)

// ---------------- device scratch (zero-initialized at module load) ----------------
__device__ __align__(16) float g_h[NN*H];
__device__ __align__(16) __half g_x1h[NN*H];
__device__ __align__(16) __half g_As0[(size_t)NN*K2];    // h split
__device__ __align__(16) __half g_As1[(size_t)NN*K2];    // msg (hi only used)
__device__ __align__(16) __half g_As2[(size_t)NN*K2];    // m1 split
__device__ __align__(16) __half g_Ast[(size_t)NL*MT*K2]; // tmp split (table)
__device__ __align__(16) __half g_Bw[(size_t)18*HK*H + 1024];  // lin1,l2w,ilw (fp16)
__device__ __align__(16) __half g_Bw2[(size_t)NL*HK*H + 1024]; // w2 (fp16)
__device__ __align__(16) float g_ea[NC*G], g_C[NC];
__device__ __align__(16) __half g_Th[NL*NC*H];   // coarse fp16 filter tables
__device__ int   g_nbr[NN*KM], g_base[NN*KM], g_cnt[NN];
__device__ __align__(16) float g_w4[NN*KM*4];

__device__ __forceinline__ float sspf(float x){
    float r = (x > 0.f) ? (x + log1pf(expf(-x))) : log1pf(expf(x));
    return r - 0.69314718055994530942f;
}

// A' split store (half2): hi block at 0, lo block at +608
__device__ __forceinline__ void split_store(__half* base, size_t off,
                                            float v0, float v1){
    __half2 hi2 = __floats2half2_rn(v0, v1);
    __half2 lo2 = __floats2half2_rn(v0 - __half2float(__low2half(hi2)),
                                    v1 - __half2float(__high2half(hi2)));
    __half2* dp = reinterpret_cast<__half2*>(base + off);
    dp[0]   = hi2;
    dp[304] = lo2;
}

// ---- fused setup: build_graph | smear | embed | wsplit, role by blockIdx ----
__global__ void __launch_bounds__(256) setup_all(
        const float* __restrict__ pos, const float* __restrict__ emb,
        const int* __restrict__ z, const float* __restrict__ lin1,
        const float* __restrict__ l2w, const float* __restrict__ ilw,
        const float* __restrict__ w2){
    int blk = blockIdx.x;
    int t = threadIdx.x;
    if(blk < NN){
        // ---- graph build for node blk (threads 0-127 active; barriers convergent) ----
        __shared__ float sx[NPG], sy[NPG], sz[NPG], sd2[NPG];
        __shared__ int scnt;
        int i = blk, b = i/NPG, il = i - b*NPG;
        bool act = t < NPG;
        const float* pg = pos + (size_t)b*NPG*3;
        if(act){ sx[t]=pg[t*3]; sy[t]=pg[t*3+1]; sz[t]=pg[t*3+2]; }
        if(t==0) scnt=0;
        __syncthreads();
        bool ok = false; float d2 = 0.f;
        if(act){
            float dx=__fsub_rn(sx[il],sx[t]), dy=__fsub_rn(sy[il],sy[t]), dz=__fsub_rn(sz[il],sz[t]);
            d2=__fadd_rn(__fadd_rn(__fmul_rn(dx,dx),__fmul_rn(dy,dy)),__fmul_rn(dz,dz));
            ok = (d2<=100.0f) && (t!=il);
            sd2[t] = ok ? d2 : 3.0e38f;
        }
        __syncthreads();
        int rank=0;
        if(act && ok){
            #pragma unroll 8
            for(int q=0;q<NPG;q++){ float o=sd2[q]; rank += (o<d2)||(o==d2 && q<t); }
            atomicAdd(&scnt,1);
        }
        __syncthreads();
        if(t==0) g_cnt[i] = min(scnt,KM);
        if(act && ok && rank<KM){
            float d = sqrtf(d2);
            float u = d * (1.0f/D0);
            int s = (int)u; if(s>255) s=255; if(s<0) s=0;
            float tt = u - (float)s;
            float t2=tt*tt, t3=t2*tt;
            int e=i*KM+rank;
            g_nbr[e]=b*NPG+t; g_base[e]=s*H;
            g_w4[e*4+0]=0.5f*(-t3+2.f*t2-tt);
            g_w4[e*4+1]=0.5f*(3.f*t3-5.f*t2+2.f);
            g_w4[e*4+2]=0.5f*(-3.f*t3+4.f*t2+tt);
            g_w4[e*4+3]=0.5f*(t3-t2);
        }
    } else if(blk < SB_EMBED){
        // ---- gaussian smearing + cutoff ----
        int idx = (blk - SB_SMEAR)*256 + t;
        if(idx >= NC*G) return;
        int q = idx/G, g = idx - q*G;
        float d = (float)(q-1)*D0;
        float step = 10.0f/49.0f;
        float x = d - (float)g*step;
        g_ea[idx] = expf((-0.5f/(step*step))*x*x);
        if(g==0) g_C[q] = 0.5f*(cosf(d*0.31415926535897932f)+1.0f);
    } else if(blk < SB_WSPLIT){
        // ---- embedding gather + h split ----
        int idx = (blk - SB_EMBED)*256 + t;
        int i = idx/H, c = idx - i*H;
        float v = emb[z[i]*H + c];
        g_h[idx] = v;
        __half hi = __float2half_rn(v);
        g_As0[(size_t)i*K2 + c]      = hi;
        g_As0[(size_t)i*K2 + HK + c] = __float2half_rn(v - __half2float(hi));
    } else {
        // ---- weight convert fp32 -> fp16, float4 vectorized ----
        int idx = (blk - SB_WSPLIT)*256 + t;
        const int PM = H*H/4;
        if(idx >= 24*PM) return;
        int w = idx/PM, e4 = idx - w*PM;
        int r = e4/150, c = (e4 - r*150)*4;
        int l = w>>2, kind = w&3;
        const float* src = (kind==0) ? lin1 : (kind==1) ? l2w : (kind==2) ? ilw : w2;
        float4 v = *reinterpret_cast<const float4*>(src + (size_t)l*H*H + (size_t)r*H + c);
        __half* dst = (kind<3) ? (g_Bw + (size_t)(l*3+kind)*HK*H)
                               : (g_Bw2 + (size_t)l*HK*H);
        __half2* d2 = reinterpret_cast<__half2*>(dst + (size_t)r*H + c);
        d2[0] = __floats2half2_rn(v.x, v.y);
        d2[1] = __floats2half2_rn(v.z, v.w);
    }
}

// ---- aggregation (R13 form): cubic interp fp16 table * fp16 x1; hi-only output ----
__global__ void __launch_bounds__(320) agg(int l){
    int i = blockIdx.x, t = threadIdx.x;
    __shared__ int s_j[KM], s_b[KM], s_cnt;
    __shared__ float4 s_w[KM];
    if(t==0) s_cnt = g_cnt[i];
    if(t<KM){
        int e=i*KM+t;
        s_j[t]=g_nbr[e]*H; s_b[t]=g_base[e];
        s_w[t]=*reinterpret_cast<const float4*>(&g_w4[e*4]);
    }
    __syncthreads();
    if(t >= 300) return;
    int h = t*2;
    const __half* T = g_Th + (size_t)l*NC*H;
    int cnt = s_cnt;
    float ax = 0.f, ay = 0.f;
    #pragma unroll 2
    for(int k=0;k<cnt;k++){
        const __half2* tp = reinterpret_cast<const __half2*>(T + s_b[k] + h);
        float2 t0=__half22float2(__ldg(tp));
        float2 t1=__half22float2(__ldg(tp+300));
        float2 t2=__half22float2(__ldg(tp+600));
        float2 t3=__half22float2(__ldg(tp+900));
        float2 x2=__half22float2(__ldg(reinterpret_cast<const __half2*>(&g_x1h[s_j[k]+h])));
        float4 w = s_w[k];
        float vx = w.x*t0.x + w.y*t1.x + w.z*t2.x + w.w*t3.x;
        float vy = w.x*t0.y + w.y*t1.y + w.z*t2.y + w.w*t3.y;
        ax = fmaf(vx, x2.x, ax);
        ay = fmaf(vy, x2.y, ay);
    }
    // single-term fp16 msg (lo block unused by bgemm1<NIT1>)
    *reinterpret_cast<__half2*>(&g_As1[(size_t)i*K2 + h]) = __floats2half2_rn(ax, ay);
}

// ---- mma / cp.async helpers ----
__device__ __forceinline__ void ldsm4(unsigned* r, unsigned addr){
    asm volatile("ldmatrix.sync.aligned.m8n8.x4.shared.b16 {%0,%1,%2,%3}, [%4];"
        : "=r"(r[0]),"=r"(r[1]),"=r"(r[2]),"=r"(r[3]) : "r"(addr));
}
__device__ __forceinline__ void ldsm4t(unsigned* r, unsigned addr){
    asm volatile("ldmatrix.sync.aligned.m8n8.x4.trans.shared.b16 {%0,%1,%2,%3}, [%4];"
        : "=r"(r[0]),"=r"(r[1]),"=r"(r[2]),"=r"(r[3]) : "r"(addr));
}
__device__ __forceinline__ void mma16816(float* c, const unsigned* a, unsigned b0, unsigned b1){
    asm volatile("mma.sync.aligned.m16n8k16.row.col.f32.f16.f16.f32 "
        "{%0,%1,%2,%3}, {%4,%5,%6,%7}, {%8,%9}, {%0,%1,%2,%3};"
        : "+f"(c[0]),"+f"(c[1]),"+f"(c[2]),"+f"(c[3])
        : "r"(a[0]),"r"(a[1]),"r"(a[2]),"r"(a[3]), "r"(b0),"r"(b1));
}
#define CPA16(dst,src) asm volatile("cp.async.cg.shared.global [%0], [%1], 16;\n"::"r"(dst),"l"(src))
#define CPC()  asm volatile("cp.async.commit_group;\n")
#define CPW2() asm volatile("cp.async.wait_group 2;\n" ::: "memory")
#define CPW0() asm volatile("cp.async.wait_group 0;\n" ::: "memory")

#define ASTG (32*40*2)
#define BSTG (32*72*2)

// 256 threads, 8 warps (2m x 4n), 32x64 CTA tile, warp tile 16x16, 4-stage cp.async.
struct Frag { unsigned aF[2]; unsigned bF[2]; unsigned aD, bD; };

__device__ __forceinline__ Frag make_frag(
        __half (*As)[32][40], __half (*Bs)[32][72],
        int wm, int wn, int lane, int arow, int acol, int brow, int bcol){
    Frag f;
    f.aD = (unsigned)__cvta_generic_to_shared(&As[0][arow][acol]);
    f.bD = (unsigned)__cvta_generic_to_shared(&Bs[0][brow][bcol]);
    #pragma unroll
    for(int s=0;s<2;s++)
        f.aF[s] = (unsigned)__cvta_generic_to_shared(
            &As[0][wm + (lane&15)][s*16 + (lane>>4)*8]);
    #pragma unroll
    for(int s=0;s<2;s++)
        f.bF[s] = (unsigned)__cvta_generic_to_shared(
            &Bs[0][s*16 + (lane&15)][wn + (lane>>4)*8]);
    return f;
}

// NITER k-blocks over A; B has 19 blocks, reused for blocks 19..37
template<int NITER>
__device__ __forceinline__ void gemm_mainloop(
        const __half* aptr, const __half* bptr, bool aload,
        const Frag& f, float acc[2][4]){
    if(aload) CPA16(f.aD, aptr);
    CPA16(f.bD, bptr); CPC();
    if(aload) CPA16(f.aD+ASTG, aptr+32);
    CPA16(f.bD+BSTG, bptr+(size_t)32*H); CPC();
    for(int it=0; it<NITER; it++){
        int pre = it+2;
        if(pre < NITER){
            int sb = pre & 3;
            int bm = (pre < 19) ? pre : pre - 19;
            if(aload) CPA16(f.aD + sb*ASTG, aptr + pre*32);
            CPA16(f.bD + sb*BSTG, bptr + (size_t)(bm*32)*H);
        }
        CPC();
        if(it < NITER-2) CPW2(); else CPW0();
        __syncthreads();
        unsigned ao = (it&3)*ASTG, bo = (it&3)*BSTG;
        #pragma unroll
        for(int s=0;s<2;s++){
            unsigned af[4], bf[4];
            ldsm4 (af, f.aF[s] + ao);
            ldsm4t(bf, f.bF[s] + bo);
            mma16816(acc[0], af, bf[0], bf[1]);
            mma16816(acc[1], af, bf[2], bf[3]);
        }
    }
}

// ---- node GEMM with fused epilogue ----
// EPI 0: -> x1h fp16. EPI 1: ssp(+bias) -> split. EPI 2: +bias+h residual -> h & split.
template<int EPI, int NITER>
__global__ void __launch_bounds__(256) bgemm(const __half* __restrict__ Ap,
        const __half* __restrict__ Bp, const float* __restrict__ bias,
        float* __restrict__ hbuf, __half* __restrict__ sout,
        __half* __restrict__ x1out){
    __shared__ __half As[4][32][40];
    __shared__ __half Bs[4][32][72];
    int tid=threadIdx.x, warp=tid>>5, lane=tid&31;
    int m0=blockIdx.y*32, n0=blockIdx.x*64;
    int wm=(warp>>2)*16, wn=(warp&3)*16;
    int arow=(tid&127)>>2, acol=(tid&3)*8;
    int brow=tid>>3, bcol=(tid&7)*8;
    bool aload = tid < 128;
    Frag f = make_frag(As, Bs, wm, wn, lane, arow, acol, brow, bcol);
    float acc[2][4];
    #pragma unroll
    for(int ni=0;ni<2;ni++)
        #pragma unroll
        for(int q=0;q<4;q++) acc[ni][q]=0.f;
    const __half* aptr = Ap + (size_t)(m0+arow)*K2 + acol;
    const __half* bptr = Bp + (size_t)brow*H + n0 + bcol;
    gemm_mainloop<NITER>(aptr, bptr, aload, f, acc);

    #pragma unroll
    for(int ni=0;ni<2;ni++){
        int c0 = n0 + wn + ni*8 + (lane&3)*2;
        if(c0 >= 600) continue;
        #pragma unroll
        for(int hf=0; hf<2; hf++){
            int r = m0 + wm + (lane>>2) + hf*8;
            float v0 = acc[ni][hf*2], v1 = acc[ni][hf*2+1];
            if(EPI==0){
                *reinterpret_cast<__half2*>(x1out + (size_t)r*H + c0)
                    = __floats2half2_rn(v0, v1);
            } else {
                v0 += bias[c0]; v1 += bias[c0+1];
                if(EPI==1){
                    v0 = sspf(v0); v1 = sspf(v1);
                } else {
                    float2 hv = *reinterpret_cast<float2*>(hbuf + (size_t)r*H + c0);
                    v0 += hv.x; v1 += hv.y;
                    *reinterpret_cast<float2*>(hbuf + (size_t)r*H + c0) = make_float2(v0, v1);
                }
                split_store(sout, (size_t)r*K2 + c0, v0, v1);
            }
        }
    }
}

// ---- table GEMM: per layer, T = (tmp' @ w2 + b2) * C -> fp16 table ----
__global__ void __launch_bounds__(256) tbgemm(const float* __restrict__ b2){
    __shared__ __half As[4][32][40];
    __shared__ __half Bs[4][32][72];
    int zb = blockIdx.z;
    int tid=threadIdx.x, warp=tid>>5, lane=tid&31;
    int m0=blockIdx.y*32, n0=blockIdx.x*64;
    int wm=(warp>>2)*16, wn=(warp&3)*16;
    int arow=(tid&127)>>2, acol=(tid&3)*8;
    int brow=tid>>3, bcol=(tid&7)*8;
    bool aload = tid < 128;
    Frag f = make_frag(As, Bs, wm, wn, lane, arow, acol, brow, bcol);
    float acc[2][4];
    #pragma unroll
    for(int ni=0;ni<2;ni++)
        #pragma unroll
        for(int q=0;q<4;q++) acc[ni][q]=0.f;
    const __half* aptr = g_Ast + (size_t)zb*MT*K2 + (size_t)(m0+arow)*K2 + acol;
    const __half* bptr = g_Bw2 + (size_t)zb*HK*H + (size_t)brow*H + n0 + bcol;
    gemm_mainloop<NIT2>(aptr, bptr, aload, f, acc);

    const float* bias = b2 + (size_t)zb*H;
    #pragma unroll
    for(int ni=0;ni<2;ni++){
        int c0 = n0 + wn + ni*8 + (lane&3)*2;
        if(c0 >= 600) continue;
        #pragma unroll
        for(int hf=0; hf<2; hf++){
            int r = m0 + wm + (lane>>2) + hf*8;
            if(r >= NC) continue;
            float cc = g_C[r];
            float v0 = (acc[ni][hf*2]   + bias[c0])   * cc;
            float v1 = (acc[ni][hf*2+1] + bias[c0+1]) * cc;
            *reinterpret_cast<__half2*>(g_Th + (size_t)zb*NC*H + (size_t)r*H + c0)
                = __floats2half2_rn(v0, v1);
        }
    }
}

// ---- table stage-1 (K=50) FFMA GEMM, epilogue: ssp + direct fp16 split ----
__global__ void __launch_bounds__(256) sgemm1(const float* __restrict__ w1,
        const float* __restrict__ b1){
    int zb = blockIdx.z;
    const float* A = g_ea;
    const float* B = w1 + (size_t)zb*G*H;
    const float* bias = b1 + (size_t)zb*H;
    const int BM=64, BN=64, BK=10;
    __shared__ float As[BK][BM], Bs[BK][BN];
    int tid=threadIdx.x, tx=tid&15, ty=tid>>4;
    int m0=blockIdx.y*BM, n0=blockIdx.x*BN;
    int ar=tid&63, ac=tid>>6;
    int br=tid>>6, bc=(tid&63);
    float acc[4][4];
    #pragma unroll
    for(int a=0;a<4;a++)
        #pragma unroll
        for(int c=0;c<4;c++) acc[a][c]=0.f;
    for(int k0=0;k0<G;k0+=BK){
        #pragma unroll
        for(int u=0;u<3;u++){
            int kk = ac + u*4;
            if(kk<BK){
                int gm=m0+ar, gk=k0+kk;
                As[kk][ar] = (gm<NC && gk<G) ? A[(size_t)gm*G+gk] : 0.f;
            }
        }
        #pragma unroll
        for(int u=0;u<3;u++){
            int kk = br + u*4;
            if(kk<BK){
                int gk=k0+kk, gn=n0+bc;
                Bs[kk][bc] = (gk<G && gn<H) ? B[(size_t)gk*H+gn] : 0.f;
            }
        }
        __syncthreads();
        #pragma unroll
        for(int kk=0;kk<BK;kk++){
            float4 av=*reinterpret_cast<const float4*>(&As[kk][ty<<2]);
            float4 bv=*reinterpret_cast<const float4*>(&Bs[kk][tx<<2]);
            float a0=av.x,a1=av.y,a2=av.z,a3=av.w;
            float b0=bv.x,b1=bv.y,b2=bv.z,b3=bv.w;
            acc[0][0]=fmaf(a0,b0,acc[0][0]); acc[0][1]=fmaf(a0,b1,acc[0][1]);
            acc[0][2]=fmaf(a0,b2,acc[0][2]); acc[0][3]=fmaf(a0,b3,acc[0][3]);
            acc[1][0]=fmaf(a1,b0,acc[1][0]); acc[1][1]=fmaf(a1,b1,acc[1][1]);
            acc[1][2]=fmaf(a1,b2,acc[1][2]); acc[1][3]=fmaf(a1,b3,acc[1][3]);
            acc[2][0]=fmaf(a2,b0,acc[2][0]); acc[2][1]=fmaf(a2,b1,acc[2][1]);
            acc[2][2]=fmaf(a2,b2,acc[2][2]); acc[2][3]=fmaf(a2,b3,acc[2][3]);
            acc[3][0]=fmaf(a3,b0,acc[3][0]); acc[3][1]=fmaf(a3,b1,acc[3][1]);
            acc[3][2]=fmaf(a3,b2,acc[3][2]); acc[3][3]=fmaf(a3,b3,acc[3][3]);
        }
        __syncthreads();
    }
    #pragma unroll
    for(int ii=0;ii<4;ii++){
        int m=m0+(ty<<2)+ii;
        if(m>=NC) continue;
        __half* row = g_Ast + (size_t)(zb*MT + m)*K2;
        #pragma unroll
        for(int jj=0;jj<4;jj++){
            int n=n0+(tx<<2)+jj;
            if(n>=H) continue;
            float v = sspf(acc[ii][jj] + bias[n]);
            __half hi = __float2half_rn(v);
            row[n]      = hi;
            row[HK + n] = __float2half_rn(v - __half2float(hi));
        }
    }
}

// ---- fused mean-pool + final linear ----
__global__ void __launch_bounds__(600) poolfin(const float* __restrict__ pw,
        const float* __restrict__ pb, float* __restrict__ out){
    int b = blockIdx.x, h = threadIdx.x;
    __shared__ float sp[H];
    const float* p = g_h + (size_t)b*NPG*H + h;
    float s = 0.f;
    #pragma unroll 8
    for(int n=0;n<NPG;n++) s += p[(size_t)n*H];
    sp[h] = s * (1.0f/NPG);
    __syncthreads();
    float o = pb[h];
    for(int k=0;k<H;k++) o = fmaf(sp[k], pw[(size_t)k*H+h], o);
    out[(size_t)b*H + h] = o;
}

extern "C" void kernel_launch(void* const* d_in, const int* in_sizes, int n_in,
                              void* d_out, int out_size){
    // dict order: z,pos,emb,w1,b1,w2,b2,lin1,l2w,l2b,ilw,ilb,pw,pb
    int map[14] = {0,1,2,3,4,5,6,7,8,9,10,11,12,13};
    if(!(in_sizes[0]==1024 && in_sizes[1]==3072)){
        int sig[14] = {13,0,1,2,3,4,5,6,7,8,9,10,11,12};
        for(int i=0;i<14;i++) map[i]=sig[i];
    }
    const int*   z    = (const int*)  d_in[map[0]];
    const float* posv = (const float*)d_in[map[1]];
    const float* emb  = (const float*)d_in[map[2]];
    const float* w1   = (const float*)d_in[map[3]];
    const float* b1   = (const float*)d_in[map[4]];
    const float* w2   = (const float*)d_in[map[5]];
    const float* b2   = (const float*)d_in[map[6]];
    const float* lin1 = (const float*)d_in[map[7]];
    const float* l2w  = (const float*)d_in[map[8]];
    const float* l2b  = (const float*)d_in[map[9]];
    const float* ilw  = (const float*)d_in[map[10]];
    const float* ilb  = (const float*)d_in[map[11]];
    const float* pw   = (const float*)d_in[map[12]];
    const float* pb   = (const float*)d_in[map[13]];
    float* out = (float*)d_out;

    float *p_h;
    __half *p_As0,*p_As1,*p_As2,*p_Bw,*p_x1h;
    cudaGetSymbolAddress((void**)&p_h,   g_h);
    cudaGetSymbolAddress((void**)&p_As0, g_As0);
    cudaGetSymbolAddress((void**)&p_As1, g_As1);
    cudaGetSymbolAddress((void**)&p_As2, g_As2);
    cudaGetSymbolAddress((void**)&p_Bw,  g_Bw);
    cudaGetSymbolAddress((void**)&p_x1h, g_x1h);

    // fused setup: graph | smear | embed | weight convert (one launch)
    setup_all<<<NB_SETUP, 256>>>(posv, emb, z, lin1, l2w, ilw, w2);

    // table build: stage-1 FFMA (K=50, fused split) -> tensor-core stage-2
    dim3 gT1((H+63)/64, (NC+63)/64, NL);
    sgemm1<<<gT1, 256>>>(w1, b1);
    dim3 gTB((H+63)/64, MT/32, NL);   // 10 x 10 x 6
    tbgemm<<<gTB, 256>>>(b2);

    dim3 gG(10, 32);   // 320 blocks
    for(int l=0;l<NL;l++){
        const __half* Blin1 = p_Bw + (size_t)(l*3+0)*HK*H;
        const __half* Bl2w  = p_Bw + (size_t)(l*3+1)*HK*H;
        const __half* Bilw  = p_Bw + (size_t)(l*3+2)*HK*H;
        // x1 = h @ lin1 -> fp16 (1-term A)
        bgemm<0,NIT1><<<gG,256>>>(p_As0, Blin1, nullptr, nullptr, nullptr, p_x1h);
        agg<<<NN, 320>>>(l);
        // m1 = ssp(msg @ l2w + l2b) -> split (1-term fp16 msg A)
        bgemm<1,NIT1><<<gG,256>>>(p_As1, Bl2w, l2b+(size_t)l*H, nullptr, p_As2, nullptr);
        // h = h + (m1 @ ilw + ilb); emits h split for next layer (2-term)
        bgemm<2,NIT2><<<gG,256>>>(p_As2, Bilw, ilb+(size_t)l*H, p_h, p_As0, nullptr);
    }
    poolfin<<<NB, H>>>(pw, pb, out);
}